// round 6
// baseline (speedup 1.0000x reference)
#include <cuda_runtime.h>
#include <math.h>

typedef unsigned long long ull;

#define BDIM 128
#define NPTS 64
#define PI_F      3.14159265358979f
#define INV_PI_F  0.318309886183791f
#define MAGIC_F   12582912.0f
#define EPS_U     3.1830989e-5f   // 1e-4 / pi

__device__ __forceinline__ ull pack2(float lo, float hi) {
    ull r; asm("mov.b64 %0, {%1, %2};" : "=l"(r) : "f"(lo), "f"(hi)); return r;
}
__device__ __forceinline__ void unpack2(ull v, float& lo, float& hi) {
    asm("mov.b64 {%0, %1}, %2;" : "=f"(lo), "=f"(hi) : "l"(v));
}
__device__ __forceinline__ ull fma2(ull a, ull b, ull c) {
    ull d; asm("fma.rn.f32x2 %0, %1, %2, %3;" : "=l"(d) : "l"(a), "l"(b), "l"(c)); return d;
}
__device__ __forceinline__ ull mul2(ull a, ull b) {
    ull d; asm("mul.rn.f32x2 %0, %1, %2;" : "=l"(d) : "l"(a), "l"(b)); return d;
}
__device__ __forceinline__ ull add2(ull a, ull b) {
    ull d; asm("add.rn.f32x2 %0, %1, %2;" : "=l"(d) : "l"(a), "l"(b)); return d;
}
__device__ __forceinline__ float rcp_approx(float x) {
    float r; asm("rcp.approx.f32 %0, %1;" : "=f"(r) : "f"(x)); return r;
}
__device__ __forceinline__ float fneg_bits(float x) {
    return __int_as_float(__float_as_int(x) ^ 0x80000000);
}

__global__ __launch_bounds__(BDIM)
void scatter_polygon_kernel(const float* __restrict__ points,
                            const float* __restrict__ phi,
                            float* __restrict__ out,
                            int B, int N) {
    __shared__ float4 spts[NPTS / 2];   // pairs of points, 16B-aligned

    const int b = blockIdx.y;
    const int n = blockIdx.x * BDIM + threadIdx.x;

    reinterpret_cast<float*>(spts)[threadIdx.x] = points[b * 2 * NPTS + threadIdx.x];
    __syncthreads();

    if (n >= N) return;

    // Per-angle constants — accurate libm sincos (phi near pi/2 -> |q| tiny,
    // scale huge; needs exact reduction).
    float sphi, cphi;
    sincosf(phi[n], &sphi, &cphi);
    const float qx = cphi;
    const float qy = sphi - 1.0f;
    const float scale = 1.0f / fabsf(qx * qx + qy * qy);
    const float qxp = qx * INV_PI_F;
    const float qyp = qy * INV_PI_F;

    // Broadcast packed constants (same value both lanes).
    const ull QXP2   = pack2(qxp, qxp);
    const ull QYP2   = pack2(qyp, qyp);
    const ull NQYP2  = pack2(-qyp, -qyp);
    const ull MAGIC2 = pack2(MAGIC_F, MAGIC_F);
    const ull M1     = pack2(-1.0f, -1.0f);
    const ull PIV    = pack2(PI_F, PI_F);
    const ull ONEV   = pack2(1.0f, 1.0f);
    const ull MHALF  = pack2(-0.5f, -0.5f);
    const ull S11 = pack2(-2.5052108e-8f, -2.5052108e-8f);
    const ull S9  = pack2( 2.7557319e-6f,  2.7557319e-6f);
    const ull S7  = pack2(-1.9841270e-4f, -1.9841270e-4f);
    const ull S5  = pack2( 8.3333333e-3f,  8.3333333e-3f);
    const ull S3  = pack2(-1.6666667e-1f, -1.6666667e-1f);
    const ull D12 = pack2( 2.0876757e-9f,  2.0876757e-9f);
    const ull D10 = pack2(-2.7557319e-7f, -2.7557319e-7f);
    const ull D8  = pack2( 2.4801587e-5f,  2.4801587e-5f);
    const ull D6  = pack2(-1.3888889e-3f, -1.3888889e-3f);
    const ull D4  = pack2( 4.1666667e-2f,  4.1666667e-2f);

    // Packed eval of TWO points (lane0 = point a, lane1 = point b):
    // u = (p.q)/pi, hc = (p.q_cross)/pi, (s,c) = sincos(p.q), mod-pi reduced.
    auto eval2 = [&](float ax, float ay, float bx, float by,
                     float& u0, float& u1, float& h0, float& h1,
                     float& s0, float& s1, float& c0, float& c1) {
        const ull PX = pack2(ax, bx);
        const ull PY = pack2(ay, by);
        const ull U  = fma2(PX, QXP2, mul2(PY, QYP2));
        const ull HC = fma2(PX, NQYP2, mul2(PY, QXP2));
        const ull T  = add2(U, MAGIC2);
        const ull NF = fma2(MAGIC2, M1, T);   // round(u)
        const ull FR = fma2(NF, M1, U);       // u - n (exact)
        const ull R  = mul2(FR, PIV);
        const ull R2 = mul2(R, R);
        const ull R3 = mul2(R2, R);
        ull W = fma2(R2, S11, S9);
        W = fma2(R2, W, S7);
        W = fma2(R2, W, S5);
        W = fma2(R2, W, S3);
        const ull SP = fma2(R3, W, R);
        ull V = fma2(R2, D12, D10);
        V = fma2(R2, V, D8);
        V = fma2(R2, V, D6);
        V = fma2(R2, V, D4);
        V = fma2(R2, V, MHALF);
        const ull CP = fma2(R2, V, ONEV);

        float t0, t1, sp0, sp1, cp0, cp1;
        unpack2(U, u0, u1);
        unpack2(HC, h0, h1);
        unpack2(T, t0, t1);
        unpack2(SP, sp0, sp1);
        unpack2(CP, cp0, cp1);
        const int g0 = __float_as_int(t0) << 31;   // (-1)^n sign bit
        const int g1 = __float_as_int(t1) << 31;
        s0 = __int_as_float(__float_as_int(sp0) ^ g0);
        s1 = __int_as_float(__float_as_int(sp1) ^ g1);
        c0 = __int_as_float(__float_as_int(cp0) ^ g0);
        c1 = __int_as_float(__float_as_int(cp1) ^ g1);
    };

    float sum_r = 0.0f, sum_i = 0.0f;

    // prev = point[NPTS-1] (edge k: p0 = point[k-1 mod P])
    float up, hp, sprev, cprev;
    {
        const float4 pl = spts[NPTS / 2 - 1];
        float d0, d1, e0, e1, f0, f1, g0, g1;
        eval2(pl.z, pl.w, pl.z, pl.w, d0, d1, e0, e1, f0, f1, g0, g1);
        up = d0; hp = e0; sprev = f0; cprev = g0;
    }

    // One scalar edge step: accumulate edge (prev -> cur), update prev state.
    auto edge = [&](float uc, float hc, float sc, float cc) {
        const float du = uc - up;             // ddq / pi
        const float dc = hc - hp;             // ddqc / pi
        const float g  = dc * rcp_approx(du); // ddqc / ddq
        const float dq = PI_F * dc;           // ddqc
        const bool big = fabsf(du) >= EPS_U;
        const float fr = big ? g : dq;
        const float fi = big ? g : fneg_bits(dq);
        const float vr = big ? (cprev - cc) : sprev;
        const float vi = big ? (sprev - sc) : cprev;
        sum_r = fmaf(fr, vr, sum_r);
        sum_i = fmaf(fi, vi, sum_i);
        up = uc; hp = hc; sprev = sc; cprev = cc;
    };

#pragma unroll 8
    for (int kk = 0; kk < NPTS / 2; ++kk) {
        const float4 pc = spts[kk];           // points 2kk (x,y), 2kk+1 (z,w)
        float u0, u1, h0, h1, s0, s1, c0, c1;
        eval2(pc.x, pc.y, pc.z, pc.w, u0, u1, h0, h1, s0, s1, c0, c1);
        edge(u0, h0, s0, c0);
        edge(u1, h1, s1, c1);
    }

    out[(b * 2 + 0) * N + n] = scale * sum_r;
    out[(b * 2 + 1) * N + n] = scale * sum_i;
}

extern "C" void kernel_launch(void* const* d_in, const int* in_sizes, int n_in,
                              void* d_out, int out_size) {
    const float* points = (const float*)d_in[0];  // [B, 64, 2] f32
    const float* phi    = (const float*)d_in[1];  // [N] f32
    float* out = (float*)d_out;                   // [B, 2, N] f32

    const int N = in_sizes[1];
    const int B = in_sizes[0] / (2 * NPTS);

    dim3 grid((N + BDIM - 1) / BDIM, B);
    scatter_polygon_kernel<<<grid, BDIM>>>(points, phi, out, B, N);
}

// round 7
// speedup vs baseline: 1.0708x; 1.0708x over previous
#include <cuda_runtime.h>
#include <math.h>

typedef unsigned long long ull;

#define BDIM 128
#define NPTS 64
#define PI_F      3.14159265358979f
#define INV_PI_F  0.318309886183791f
#define MAGIC_F   12582912.0f
#define EPS_U     3.1830989e-5f   // 1e-4 / pi

__device__ __forceinline__ ull pack2(float lo, float hi) {
    ull r; asm("mov.b64 %0, {%1, %2};" : "=l"(r) : "f"(lo), "f"(hi)); return r;
}
__device__ __forceinline__ void unpack2(ull v, float& lo, float& hi) {
    asm("mov.b64 {%0, %1}, %2;" : "=f"(lo), "=f"(hi) : "l"(v));
}
__device__ __forceinline__ ull fma2(ull a, ull b, ull c) {
    ull d; asm("fma.rn.f32x2 %0, %1, %2, %3;" : "=l"(d) : "l"(a), "l"(b), "l"(c)); return d;
}
__device__ __forceinline__ ull mul2(ull a, ull b) {
    ull d; asm("mul.rn.f32x2 %0, %1, %2;" : "=l"(d) : "l"(a), "l"(b)); return d;
}
__device__ __forceinline__ ull add2(ull a, ull b) {
    ull d; asm("add.rn.f32x2 %0, %1, %2;" : "=l"(d) : "l"(a), "l"(b)); return d;
}
__device__ __forceinline__ float rcp_approx(float x) {
    float r; asm("rcp.approx.f32 %0, %1;" : "=f"(r) : "f"(x)); return r;
}

__global__ __launch_bounds__(BDIM)
void scatter_polygon_kernel(const float* __restrict__ points,
                            const float* __restrict__ phi,
                            float* __restrict__ out,
                            int B, int N) {
    // SoA: pairs of consecutive x (or y) coords are 8B-aligned -> LDS.64
    // lands directly in a packed register pair (no pack MOVs).
    __shared__ __align__(8) float sx[NPTS];
    __shared__ __align__(8) float sy[NPTS];

    const int b = blockIdx.y;
    const int n = blockIdx.x * BDIM + threadIdx.x;

    if (threadIdx.x < NPTS) {
        const float2 p = reinterpret_cast<const float2*>(points)[b * NPTS + threadIdx.x];
        sx[threadIdx.x] = p.x;
        sy[threadIdx.x] = p.y;
    }
    __syncthreads();

    if (n >= N) return;

    // Per-angle constants — accurate libm sincos (phi ~ pi/2 -> |q| tiny,
    // scale huge; needs exact reduction).
    float sphi, cphi;
    sincosf(phi[n], &sphi, &cphi);
    const float qx = cphi;
    const float qy = sphi - 1.0f;
    const float scale = 1.0f / fabsf(qx * qx + qy * qy);
    const float qxp = qx * INV_PI_F;
    const float qyp = qy * INV_PI_F;

    // Packed broadcast constants.
    const ull QXP2  = pack2(qxp, qxp);
    const ull QYP2  = pack2(qyp, qyp);
    const ull NQYP2 = pack2(-qyp, -qyp);
    const ull MAGIC2  = pack2(MAGIC_F, MAGIC_F);
    const ull NMAGIC2 = pack2(-MAGIC_F, -MAGIC_F);
    const ull M1    = pack2(-1.0f, -1.0f);
    const ull ONE2  = pack2(1.0f, 1.0f);
    // sin(pi*f) = f*(PI + f2*(A3 + f2*(A5 + f2*(A7 + f2*(A9 + f2*A11)))))
    const ull PIC = pack2( 3.14159265f,  3.14159265f);
    const ull A3  = pack2(-5.16771278f, -5.16771278f);
    const ull A5  = pack2( 2.55016404f,  2.55016404f);
    const ull A7  = pack2(-0.59926453f, -0.59926453f);
    const ull A9  = pack2( 0.08214589f,  0.08214589f);
    const ull A11 = pack2(-7.3704309e-3f, -7.3704309e-3f);
    // cos(pi*f) = 1 + f2*(B2 + f2*(B4 + f2*(B6 + f2*(B8 + f2*(B10 + f2*B12)))))
    const ull B2  = pack2(-4.93480220f, -4.93480220f);
    const ull B4  = pack2( 4.05871213f,  4.05871213f);
    const ull B6  = pack2(-1.33526277f, -1.33526277f);
    const ull B8  = pack2( 0.23533063f,  0.23533063f);
    const ull B10 = pack2(-2.5806833e-2f, -2.5806833e-2f);
    const ull B12 = pack2( 1.9295864e-3f,  1.9295864e-3f);

    // Packed eval of TWO points: u = (p.q)/pi, hc = (p.q_cross)/pi,
    // (s,c) = sincos(p.q) via mod-pi reduction + Taylor in f (pi folded).
    auto eval2 = [&](ull PX, ull PY,
                     float& u0, float& u1, float& h0, float& h1,
                     float& s0, float& s1, float& c0, float& c1) {
        const ull U  = fma2(PX, QXP2, mul2(PY, QYP2));
        const ull HC = fma2(PX, NQYP2, mul2(PY, QXP2));
        const ull T  = add2(U, MAGIC2);
        const ull NF = add2(T, NMAGIC2);        // round(u)
        const ull FR = fma2(NF, M1, U);         // f = u - n (exact)
        const ull F2 = mul2(FR, FR);
        ull W = fma2(F2, A11, A9);
        W = fma2(F2, W, A7);
        W = fma2(F2, W, A5);
        W = fma2(F2, W, A3);
        W = fma2(F2, W, PIC);
        const ull SP = mul2(FR, W);             // sin(pi f)
        ull V = fma2(F2, B12, B10);
        V = fma2(F2, V, B8);
        V = fma2(F2, V, B6);
        V = fma2(F2, V, B4);
        V = fma2(F2, V, B2);
        const ull CP = fma2(F2, V, ONE2);       // cos(pi f)

        float t0, t1, sp0, sp1, cp0, cp1;
        unpack2(U, u0, u1);
        unpack2(HC, h0, h1);
        unpack2(T, t0, t1);
        unpack2(SP, sp0, sp1);
        unpack2(CP, cp0, cp1);
        const int g0 = __float_as_int(t0) << 31;   // (-1)^n sign bit
        const int g1 = __float_as_int(t1) << 31;
        s0 = __int_as_float(__float_as_int(sp0) ^ g0);
        s1 = __int_as_float(__float_as_int(sp1) ^ g1);
        c0 = __int_as_float(__float_as_int(cp0) ^ g0);
        c1 = __int_as_float(__float_as_int(cp1) ^ g1);
    };

    float sum_r = 0.0f, nsum_i = 0.0f;          // nsum_i accumulates -imag

    // prev = point[NPTS-1]
    float up, hp, sprev, cprev;
    {
        const ull PX = pack2(sx[NPTS - 1], sx[NPTS - 1]);
        const ull PY = pack2(sy[NPTS - 1], sy[NPTS - 1]);
        float uu1, hh1, ss1, cc1;
        eval2(PX, PY, up, uu1, hp, hh1, sprev, ss1, cprev, cc1);
    }

    // edge (prev -> cur): shared multiplier select, negated-imag accumulation.
    //  case1 (|ddq|>=eps): r += g*(cprev-cc);  -i += g*(sc-sprev)
    //  case2:              r += dq*sprev;      -i += dq*cprev     (dq = ddqc)
    auto edge = [&](float uc, float hc, float sc, float cc) {
        const float du = uc - up;               // ddq / pi
        const float dc = hc - hp;               // ddqc / pi
        const float g  = dc * rcp_approx(du);   // ddqc / ddq
        const float dq = PI_F * dc;             // ddqc
        const bool big = fabsf(du) >= EPS_U;
        const float f  = big ? g : dq;
        const float vr = big ? (cprev - cc) : sprev;
        const float vi = big ? (sc - sprev) : cprev;
        sum_r  = fmaf(f, vr, sum_r);
        nsum_i = fmaf(f, vi, nsum_i);
        up = uc; hp = hc; sprev = sc; cprev = cc;
    };

#pragma unroll 8
    for (int kk = 0; kk < NPTS / 2; ++kk) {
        const ull PX = reinterpret_cast<const ull*>(sx)[kk];  // x[2kk], x[2kk+1]
        const ull PY = reinterpret_cast<const ull*>(sy)[kk];
        float u0, u1, h0, h1, s0, s1, c0, c1;
        eval2(PX, PY, u0, u1, h0, h1, s0, s1, c0, c1);
        edge(u0, h0, s0, c0);
        edge(u1, h1, s1, c1);
    }

    out[(b * 2 + 0) * N + n] = scale * sum_r;
    out[(b * 2 + 1) * N + n] = -(scale * nsum_i);
}

extern "C" void kernel_launch(void* const* d_in, const int* in_sizes, int n_in,
                              void* d_out, int out_size) {
    const float* points = (const float*)d_in[0];  // [B, 64, 2] f32
    const float* phi    = (const float*)d_in[1];  // [N] f32
    float* out = (float*)d_out;                   // [B, 2, N] f32

    const int N = in_sizes[1];
    const int B = in_sizes[0] / (2 * NPTS);

    dim3 grid((N + BDIM - 1) / BDIM, B);
    scatter_polygon_kernel<<<grid, BDIM>>>(points, phi, out, B, N);
}